// round 2
// baseline (speedup 1.0000x reference)
#include <cuda_runtime.h>
#include <math.h>

#define BB 16384

// ---------------- device scratch (static, no allocation) ----------------
__device__ float g_Wcat[128 * 1280];                // [128][1024 MQK | 256 Wres]
__device__ float g_PR[(size_t)BB * 1280];           // per-row: P(1024) | R(256)
__device__ float g_U[(size_t)BB * 1024];            // u per head (4 x 256)
__device__ float g_Z1[(size_t)BB * 256];
__device__ float g_H1[(size_t)BB * 256];

// ---------------- helpers ----------------
__device__ __forceinline__ float wsum(float v) {
#pragma unroll
  for (int o = 16; o; o >>= 1) v += __shfl_xor_sync(0xffffffffu, v, o);
  return v;
}
__device__ __forceinline__ float wmax(float v) {
#pragma unroll
  for (int o = 16; o; o >>= 1) v = fmaxf(v, __shfl_xor_sync(0xffffffffu, v, o));
  return v;
}

// FMA-pipe sincos (avoid MUFU.SIN throughput wall). Valid for |z| <~ 1e4.
__device__ __forceinline__ void fast_sincos(float z, float& s, float& c) {
  float t = rintf(z * 0.63661977236758134f);  // 2/pi
  int qi = (int)t;
  float r = fmaf(t, -1.5703125f, z);
  r = fmaf(t, -4.83751296997070312e-4f, r);
  r = fmaf(t, -7.54978995489188e-8f, r);
  float r2 = r * r;
  float sp = fmaf(r2, -1.9515296e-4f, 8.3321608e-3f);
  sp = fmaf(r2, sp, -1.6666654611e-1f);
  float sinr = fmaf(r * r2, sp, r);
  float cp = fmaf(r2, -1.388731625493765e-3f, 4.166664568298827e-2f);
  cp = fmaf(r2, cp, -0.5f);
  float cosr = fmaf(r2, cp, 1.0f);
  int qq = qi & 3;
  float ss = (qq & 1) ? cosr : sinr;
  float cc = (qq & 1) ? sinr : cosr;
  s = (qq & 2) ? -ss : ss;
  c = ((qq + 1) & 2) ? -cc : cc;
}

// ---------------- K0a: MQK_h[i][j] = sum_d Wq[i,64h+d]*Wk[j,64h+d] ----------------
// grid (4 heads, 8 i-slices of 16), 256 threads
__global__ void __launch_bounds__(256) mqk_kernel(const float* __restrict__ Wq,
                                                  const float* __restrict__ Wk) {
  __shared__ float sWq[16 * 68];
  __shared__ float sWk[128 * 68];
  int h = blockIdx.x, is = blockIdx.y;
  int tid = threadIdx.x;
  // load 16 Wq rows' head slice (16 rows x 16 float4)
  {
    int il = tid >> 4, d4 = tid & 15;
    *(float4*)&sWq[il * 68 + d4 * 4] =
        *(const float4*)&Wq[(size_t)(is * 16 + il) * 256 + h * 64 + d4 * 4];
  }
  for (int jc = 0; jc < 2; jc++) {
    __syncthreads();
#pragma unroll
    for (int it = 0; it < 8; it++) {
      int f = tid + it * 256;  // 0..2047
      int j = f >> 4, d4 = f & 15;
      *(float4*)&sWk[j * 68 + d4 * 4] =
          *(const float4*)&Wk[(size_t)(jc * 128 + j) * 256 + h * 64 + d4 * 4];
    }
    __syncthreads();
    int j = tid & 127, ih = tid >> 7;
#pragma unroll 1
    for (int il = ih * 8; il < ih * 8 + 8; il++) {
      float acc = 0.f;
#pragma unroll
      for (int d = 0; d < 64; d++) acc = fmaf(sWq[il * 68 + d], sWk[j * 68 + d], acc);
      g_Wcat[(size_t)(is * 16 + il) * 1280 + h * 256 + jc * 128 + j] = acc;
    }
  }
}

__global__ void copy_wres_kernel(const float* __restrict__ Wres) {
  int i = blockIdx.x, tid = threadIdx.x;
  g_Wcat[(size_t)i * 1280 + 1024 + tid] = Wres[(size_t)i * 256 + tid];
}

// ---------------- generic fp32 GEMM, BM=64 BN=256 BK=32, 256 threads ----------------
// EPI: 0 = plain store, 1 = relu(x+bias), 2 = LN(x+bias+resid)*gamma+beta (requires gridDim.x==1)
template <int EPI>
__global__ void __launch_bounds__(256) gemm_epi(
    const float* __restrict__ A, const float* __restrict__ W, float* __restrict__ C,
    int K, int ldw, int ldc,
    const float* __restrict__ bias,
    const float* __restrict__ resid, int ldres,
    const float* __restrict__ gamma, const float* __restrict__ beta) {
  __shared__ float sA[64 * 36];
  __shared__ float sB[32 * 256];
  int tid = threadIdx.x;
  int m0 = blockIdx.y * 64, n0 = blockIdx.x * 256;
  int r0 = (tid >> 5) * 8, c0 = (tid & 31) * 8;
  float acc[8][8];
#pragma unroll
  for (int i = 0; i < 8; i++)
#pragma unroll
    for (int j = 0; j < 8; j++) acc[i][j] = 0.f;

  int kt_n = K >> 5;
  for (int kt = 0; kt < kt_n; kt++) {
    __syncthreads();
#pragma unroll
    for (int it = 0; it < 2; it++) {
      int f = tid + it * 256, r = f >> 3, kq = f & 7;
      *(float4*)&sA[r * 36 + kq * 4] =
          *(const float4*)&A[(size_t)(m0 + r) * K + kt * 32 + kq * 4];
    }
#pragma unroll
    for (int it = 0; it < 8; it++) {
      int f = tid + it * 256, kk = f >> 6, c4 = f & 63;
      *(float4*)&sB[kk * 256 + c4 * 4] =
          *(const float4*)&W[(size_t)(kt * 32 + kk) * ldw + n0 + c4 * 4];
    }
    __syncthreads();
#pragma unroll
    for (int kk = 0; kk < 32; kk++) {
      float4 b0 = *(float4*)&sB[kk * 256 + c0];
      float4 b1 = *(float4*)&sB[kk * 256 + c0 + 4];
      float bj[8] = {b0.x, b0.y, b0.z, b0.w, b1.x, b1.y, b1.z, b1.w};
      float aj[8];
#pragma unroll
      for (int i = 0; i < 8; i++) aj[i] = sA[(r0 + i) * 36 + kk];
#pragma unroll
      for (int i = 0; i < 8; i++)
#pragma unroll
        for (int j = 0; j < 8; j++) acc[i][j] = fmaf(aj[i], bj[j], acc[i][j]);
    }
  }
  // ---- epilogue ----
  float bb[8], gg[8], ee[8];
  if (EPI >= 1) {
#pragma unroll
    for (int j = 0; j < 8; j++) bb[j] = bias[n0 + c0 + j];
  }
  if (EPI == 2) {
#pragma unroll
    for (int j = 0; j < 8; j++) {
      gg[j] = gamma[n0 + c0 + j];
      ee[j] = beta[n0 + c0 + j];
    }
  }
#pragma unroll
  for (int i = 0; i < 8; i++) {
    size_t row = (size_t)(m0 + r0 + i);
    float v[8];
    if (EPI == 0) {
#pragma unroll
      for (int j = 0; j < 8; j++) v[j] = acc[i][j];
    } else if (EPI == 1) {
#pragma unroll
      for (int j = 0; j < 8; j++) v[j] = fmaxf(acc[i][j] + bb[j], 0.f);
    } else {
      float4 rr0 = *(const float4*)&resid[row * ldres + c0];
      float4 rr1 = *(const float4*)&resid[row * ldres + c0 + 4];
      float rj[8] = {rr0.x, rr0.y, rr0.z, rr0.w, rr1.x, rr1.y, rr1.z, rr1.w};
#pragma unroll
      for (int j = 0; j < 8; j++) v[j] = acc[i][j] + bb[j] + rj[j];
      float s = 0.f;
#pragma unroll
      for (int j = 0; j < 8; j++) s += v[j];
      s = wsum(s);
      float mean = s * (1.f / 256.f);
      float q = 0.f;
#pragma unroll
      for (int j = 0; j < 8; j++) {
        float d = v[j] - mean;
        q += d * d;
      }
      q = wsum(q);
      float rstd = rsqrtf(q * (1.f / 256.f) + 1e-5f);
#pragma unroll
      for (int j = 0; j < 8; j++) v[j] = (v[j] - mean) * rstd * gg[j] + ee[j];
    }
    float4 o0 = {v[0], v[1], v[2], v[3]};
    float4 o1 = {v[4], v[5], v[6], v[7]};
    *(float4*)&C[row * ldc + n0 + c0] = o0;
    *(float4*)&C[row * ldc + n0 + c0 + 4] = o1;
  }
}

// ---------------- K2: attention -> u[b, h*256+j] ----------------
// one block per b, 256 threads
__global__ void __launch_bounds__(256) attn_u_kernel(
    const float* __restrict__ x_ctx, const float* __restrict__ t_ctx,
    const float* __restrict__ freq, const float* __restrict__ phase) {
  __shared__ float kv[32 * 257];
  __shared__ float sp[1024];
  __shared__ float slog[128];
  __shared__ float sw[128];
  int b = blockIdx.x, tid = threadIdx.x;
  // kv x-part
  const float* xr = x_ctx + (size_t)b * 32 * 128;
#pragma unroll
  for (int i = 0; i < 16; i++) {
    int e = tid + i * 256;
    int l = e >> 7, j = e & 127;
    kv[l * 257 + j] = xr[e];
  }
  // kv te-part: thread t handles (l = t>>3, 8 freqs)
  {
    int l = tid >> 3, k0 = (tid & 7) * 8;
    float t = t_ctx[(size_t)b * 32 + l];
    float lt = log1pf(fmaxf(t, 0.f));
#pragma unroll
    for (int k = 0; k < 8; k++) {
      float z = fmaf(lt, freq[k0 + k], phase[k0 + k]);
      float s, c;
      fast_sincos(z, s, c);
      kv[l * 257 + 128 + k0 + k] = s;
      kv[l * 257 + 192 + k0 + k] = c;
    }
  }
  // p (1024 floats)
  {
    float4 v = *(const float4*)&g_PR[(size_t)b * 1280 + tid * 4];
    *(float4*)&sp[tid * 4] = v;
  }
  __syncthreads();
  // logits: thread -> (h = t>>6, l = (t>>1)&31, half = t&1)
  {
    int h = tid >> 6, l = (tid >> 1) & 31, half = tid & 1;
    const float* kp = &kv[l * 257 + half * 128];
    const float* pp = &sp[h * 256 + half * 128];
    float a = 0.f;
#pragma unroll 4
    for (int j = 0; j < 128; j++) a = fmaf(kp[j], pp[j], a);
    a += __shfl_xor_sync(0xffffffffu, a, 1);
    if (half == 0) slog[h * 32 + l] = a * 0.125f;
  }
  __syncthreads();
  if (tid < 128) {
    int h = tid >> 5, l = tid & 31;
    float v = slog[h * 32 + l];
    float m = wmax(v);
    float e = __expf(v - m);
    float s = wsum(e);
    sw[h * 32 + l] = e / s;
  }
  __syncthreads();
  // u: thread t owns kv-dim j=t, all 4 heads
  {
    float a0 = 0.f, a1 = 0.f, a2 = 0.f, a3 = 0.f;
#pragma unroll
    for (int l = 0; l < 32; l++) {
      float v = kv[l * 257 + tid];
      a0 = fmaf(sw[l], v, a0);
      a1 = fmaf(sw[32 + l], v, a1);
      a2 = fmaf(sw[64 + l], v, a2);
      a3 = fmaf(sw[96 + l], v, a3);
    }
    size_t o = (size_t)b * 1024 + tid;
    g_U[o] = a0;
    g_U[o + 256] = a1;
    g_U[o + 512] = a2;
    g_U[o + 768] = a3;
  }
}

// ---------------- K3: head-split GEMM agg = u_h @ Wv[:,h*64..] + LN epilogue ----------
// BM=64, BN=256 (full width), BK=16, 256 threads, grid (1, B/64)
__global__ void __launch_bounds__(256) gemm_hs_ln(
    const float* __restrict__ Wv, float* __restrict__ C,
    const float* __restrict__ bias, const float* __restrict__ resid, int ldres,
    const float* __restrict__ gamma, const float* __restrict__ beta) {
  __shared__ float sA[64 * 80];
  __shared__ float sB[16 * 256];
  int tid = threadIdx.x;
  int m0 = blockIdx.y * 64;
  int r0 = (tid >> 5) * 8, c0 = (tid & 31) * 8, hh = c0 >> 6;
  float acc[8][8];
#pragma unroll
  for (int i = 0; i < 8; i++)
#pragma unroll
    for (int j = 0; j < 8; j++) acc[i][j] = 0.f;

  for (int kt = 0; kt < 16; kt++) {
    __syncthreads();
#pragma unroll
    for (int it = 0; it < 4; it++) {
      int f = tid + it * 256;  // 0..1023
      int r = f >> 4, q = f & 15;
      int h = q >> 2, kq = q & 3;
      *(float4*)&sA[r * 80 + h * 20 + kq * 4] =
          *(const float4*)&g_U[(size_t)(m0 + r) * 1024 + h * 256 + kt * 16 + kq * 4];
    }
#pragma unroll
    for (int it = 0; it < 4; it++) {
      int f = tid + it * 256;
      int kk = f >> 6, c4 = f & 63;
      *(float4*)&sB[kk * 256 + c4 * 4] =
          *(const float4*)&Wv[(size_t)(kt * 16 + kk) * 256 + c4 * 4];
    }
    __syncthreads();
#pragma unroll
    for (int kk = 0; kk < 16; kk++) {
      float4 b0 = *(float4*)&sB[kk * 256 + c0];
      float4 b1 = *(float4*)&sB[kk * 256 + c0 + 4];
      float bj[8] = {b0.x, b0.y, b0.z, b0.w, b1.x, b1.y, b1.z, b1.w};
      float aj[8];
#pragma unroll
      for (int i = 0; i < 8; i++) aj[i] = sA[(r0 + i) * 80 + hh * 20 + kk];
#pragma unroll
      for (int i = 0; i < 8; i++)
#pragma unroll
        for (int j = 0; j < 8; j++) acc[i][j] = fmaf(aj[i], bj[j], acc[i][j]);
    }
  }
  // ---- LN epilogue: LN(acc + bias + resid) * gamma + beta ----
  float bb[8], gg[8], ee[8];
#pragma unroll
  for (int j = 0; j < 8; j++) {
    bb[j] = bias[c0 + j];
    gg[j] = gamma[c0 + j];
    ee[j] = beta[c0 + j];
  }
#pragma unroll
  for (int i = 0; i < 8; i++) {
    size_t row = (size_t)(m0 + r0 + i);
    float4 rr0 = *(const float4*)&resid[row * ldres + c0];
    float4 rr1 = *(const float4*)&resid[row * ldres + c0 + 4];
    float rj[8] = {rr0.x, rr0.y, rr0.z, rr0.w, rr1.x, rr1.y, rr1.z, rr1.w};
    float v[8];
#pragma unroll
    for (int j = 0; j < 8; j++) v[j] = acc[i][j] + bb[j] + rj[j];
    float s = 0.f;
#pragma unroll
    for (int j = 0; j < 8; j++) s += v[j];
    s = wsum(s);
    float mean = s * (1.f / 256.f);
    float q = 0.f;
#pragma unroll
    for (int j = 0; j < 8; j++) {
      float d = v[j] - mean;
      q += d * d;
    }
    q = wsum(q);
    float rstd = rsqrtf(q * (1.f / 256.f) + 1e-5f);
    float4 o0, o1;
    o0.x = (v[0] - mean) * rstd * gg[0] + ee[0];
    o0.y = (v[1] - mean) * rstd * gg[1] + ee[1];
    o0.z = (v[2] - mean) * rstd * gg[2] + ee[2];
    o0.w = (v[3] - mean) * rstd * gg[3] + ee[3];
    o1.x = (v[4] - mean) * rstd * gg[4] + ee[4];
    o1.y = (v[5] - mean) * rstd * gg[5] + ee[5];
    o1.z = (v[6] - mean) * rstd * gg[6] + ee[6];
    o1.w = (v[7] - mean) * rstd * gg[7] + ee[7];
    *(float4*)&C[row * 256 + c0] = o0;
    *(float4*)&C[row * 256 + c0 + 4] = o1;
  }
}

// ---------------- launch ----------------
extern "C" void kernel_launch(void* const* d_in, const int* in_sizes, int n_in,
                              void* d_out, int out_size) {
  const float* x_u   = (const float*)d_in[0];
  const float* x_ctx = (const float*)d_in[1];
  const float* t_ctx = (const float*)d_in[2];
  const float* freq  = (const float*)d_in[3];
  const float* phase = (const float*)d_in[4];
  const float* Wq    = (const float*)d_in[5];
  const float* Wk    = (const float*)d_in[6];
  const float* Wv    = (const float*)d_in[7];
  const float* Wres  = (const float*)d_in[8];
  const float* bres  = (const float*)d_in[9];
  const float* W1    = (const float*)d_in[10];
  const float* b1    = (const float*)d_in[11];
  const float* W2    = (const float*)d_in[12];
  const float* b2    = (const float*)d_in[13];
  const float* g1    = (const float*)d_in[14];
  const float* be1   = (const float*)d_in[15];
  const float* g2    = (const float*)d_in[16];
  const float* be2   = (const float*)d_in[17];
  float* out = (float*)d_out;

  float *pWcat, *pPR, *pZ1, *pH1;
  cudaGetSymbolAddress((void**)&pWcat, g_Wcat);
  cudaGetSymbolAddress((void**)&pPR, g_PR);
  cudaGetSymbolAddress((void**)&pZ1, g_Z1);
  cudaGetSymbolAddress((void**)&pH1, g_H1);

  // K0: build [MQK | Wres] (128 x 1280)
  mqk_kernel<<<dim3(4, 8), 256>>>(Wq, Wk);
  copy_wres_kernel<<<128, 256>>>(Wres);

  // K1: P|R = x_u @ Wcat   [16384,128] x [128,1280]
  gemm_epi<0><<<dim3(5, 256), 256>>>(x_u, pWcat, pPR, 128, 1280, 1280,
                                     nullptr, nullptr, 0, nullptr, nullptr);

  // K2: attention -> u
  attn_u_kernel<<<BB, 256>>>(x_ctx, t_ctx, freq, phase);

  // K3: z1 = LN(u_h @ Wv_h + R + bres)
  gemm_hs_ln<<<dim3(1, 256), 256>>>(Wv, pZ1, bres, pPR + 1024, 1280, g1, be1);

  // K4: h1 = relu(z1 @ W1 + b1)
  gemm_epi<1><<<dim3(1, 256), 256>>>(pZ1, W1, pH1, 256, 256, 256,
                                     b1, nullptr, 0, nullptr, nullptr);

  // K5: out = LN(h1 @ W2 + b2 + z1)
  gemm_epi<2><<<dim3(1, 256), 256>>>(pH1, W2, out, 256, 256, 256,
                                     b2, pZ1, 256, g2, be2);
}